// round 1
// baseline (speedup 1.0000x reference)
#include <cuda_runtime.h>
#include <cuda_fp16.h>
#include <cstdint>

// ---------------------------------------------------------------------------
// MultiHeadAttention: B=4, L=2048, D=512, H=8, DK=DV=64
// Pipeline:
//   f2h converts (q,k,v,wq,wv,fc) -> fp16
//   proj GEMMs (mma.sync f16) -> qh (scaled by 1/TEMP), kh, vh  [head layout]
//   scores: expS = exp(mask? -inf : qh.kh)  (fp16 scratch) + atomic rowsums
//   pv: normalize expS -> write fp32 attn output + O = Pn @ V -> xin (fp16,
//       with the reference's buffer-reinterpretation folded into the index)
//   fc GEMM -> x2 (fp32), then LayerNorm(x2 + residual q) -> y output
// ---------------------------------------------------------------------------

#define DEV static __device__ __forceinline__

constexpr int Bb = 4, Ll = 2048, Dd = 512, Hh = 8;
constexpr int BL = Bb * Ll;   // 8192
constexpr int BH = Bb * Hh;   // 32
constexpr float INV_TEMP = 0.125f;   // 1/sqrt(64)
constexpr float LN_EPS = 1e-5f;

// ------------------------- scratch (static device mem) ---------------------
__device__ __half g_q16[BL * Dd];
__device__ __half g_k16[BL * Dd];
__device__ __half g_v16[BL * Dd];
__device__ __half g_wq16[Dd * Dd];
__device__ __half g_wv16[Dd * Dd];
__device__ __half g_wf16[Dd * Dd];
__device__ __half g_qh[BL * Dd];     // (B,H,L,64) head layout, pre-scaled 1/TEMP
__device__ __half g_kh[BL * Dd];
__device__ __half g_vh[BL * Dd];
__device__ __half g_p[(size_t)BH * Ll * Ll];   // unnormalized exp scores, fp16
__device__ float  g_rowsum[BH * Ll];
__device__ __half g_xin[BL * Dd];    // FC input (already permuted), fp16
__device__ float  g_x2[BL * Dd];     // FC output fp32

// ------------------------- mma / ldmatrix helpers ---------------------------
DEV uint32_t sptr(const void* p) { return (uint32_t)__cvta_generic_to_shared(p); }

DEV void ldm_x4(uint32_t r[4], uint32_t addr) {
    asm volatile("ldmatrix.sync.aligned.m8n8.x4.shared.b16 {%0,%1,%2,%3},[%4];"
                 : "=r"(r[0]), "=r"(r[1]), "=r"(r[2]), "=r"(r[3]) : "r"(addr));
}
DEV void ldm_x4_t(uint32_t r[4], uint32_t addr) {
    asm volatile("ldmatrix.sync.aligned.m8n8.x4.trans.shared.b16 {%0,%1,%2,%3},[%4];"
                 : "=r"(r[0]), "=r"(r[1]), "=r"(r[2]), "=r"(r[3]) : "r"(addr));
}
DEV void mma16816(float c[4], const uint32_t a[4], uint32_t b0, uint32_t b1) {
    asm volatile(
        "mma.sync.aligned.m16n8k16.row.col.f32.f16.f16.f32 "
        "{%0,%1,%2,%3},{%4,%5,%6,%7},{%8,%9},{%0,%1,%2,%3};"
        : "+f"(c[0]), "+f"(c[1]), "+f"(c[2]), "+f"(c[3])
        : "r"(a[0]), "r"(a[1]), "r"(a[2]), "r"(a[3]), "r"(b0), "r"(b1));
}

// head layout index for (row r in [0,8192), col c in [0,512))
DEV size_t head_idx(int r, int c) {
    int b = r >> 11, l = r & 2047, h = c >> 6, d = c & 63;
    return ((size_t)((b << 3) | h) * 2048 + l) * 64 + d;
}

// ------------------------- small utility kernels ----------------------------
__global__ void f2h_kernel(const float* __restrict__ in, __half* __restrict__ out, int n) {
    int i = (blockIdx.x * blockDim.x + threadIdx.x) * 4;
    if (i < n) {
        float4 v = *(const float4*)(in + i);
        *(__half2*)(out + i)     = __floats2half2_rn(v.x, v.y);
        *(__half2*)(out + i + 2) = __floats2half2_rn(v.z, v.w);
    }
}
__global__ void zero_kernel(float* p, int n) {
    int i = blockIdx.x * blockDim.x + threadIdx.x;
    if (i < n) p[i] = 0.0f;
}
__global__ void invert_kernel(float* p, int n) {
    int i = blockIdx.x * blockDim.x + threadIdx.x;
    if (i < n) p[i] = 1.0f / p[i];
}

// ------------------------- generic GEMM: C = A(M,K) @ W(N,K)^T --------------
// EPI 0: out = half, head layout, (acc+bias)*scale
// EPI 1: out = float, row-major,  acc+bias
template <int EPI>
__global__ __launch_bounds__(256)
void gemm_kernel(const __half* __restrict__ A, const __half* __restrict__ W,
                 const float* __restrict__ bias, void* __restrict__ out,
                 int K, int N, float scale)
{
    constexpr int BM = 128, BN = 128, BK = 32;
    constexpr int AS = 40, BS = 40;   // padded half strides
    __shared__ __half As[BM * AS];
    __shared__ __half Bs[BN * BS];

    int tid = threadIdx.x;
    int warp = tid >> 5, lane = tid & 31;
    int wm = warp >> 1, wn = warp & 1;
    int m0 = blockIdx.y * BM, n0 = blockIdx.x * BN;

    float c[2][8][4];
#pragma unroll
    for (int i = 0; i < 2; i++)
#pragma unroll
        for (int j = 0; j < 8; j++)
#pragma unroll
            for (int k = 0; k < 4; k++) c[i][j][k] = 0.0f;

    for (int k0 = 0; k0 < K; k0 += BK) {
#pragma unroll
        for (int i = 0; i < 2; i++) {
            int u = tid + i * 256;
            int r = u >> 2, s = u & 3;
            *(int4*)&As[r * AS + s * 8] = *(const int4*)&A[(size_t)(m0 + r) * K + k0 + s * 8];
            *(int4*)&Bs[r * BS + s * 8] = *(const int4*)&W[(size_t)(n0 + r) * K + k0 + s * 8];
        }
        __syncthreads();
#pragma unroll
        for (int ks = 0; ks < 2; ks++) {
            uint32_t a[2][4];
#pragma unroll
            for (int mi = 0; mi < 2; mi++) {
                int row = wm * 32 + mi * 16 + (lane & 15);
                int col = ks * 16 + ((lane >> 4) << 3);
                ldm_x4(a[mi], sptr(&As[row * AS + col]));
            }
            uint32_t bb[4][4];
#pragma unroll
            for (int p = 0; p < 4; p++) {
                int tg = lane >> 3, idx = lane & 7;
                int row = wn * 64 + p * 16 + ((tg >> 1) << 3) + idx;
                int col = ks * 16 + ((tg & 1) << 3);
                ldm_x4(bb[p], sptr(&Bs[row * BS + col]));
            }
#pragma unroll
            for (int mi = 0; mi < 2; mi++)
#pragma unroll
                for (int p = 0; p < 4; p++) {
                    mma16816(c[mi][2 * p],     a[mi], bb[p][0], bb[p][1]);
                    mma16816(c[mi][2 * p + 1], a[mi], bb[p][2], bb[p][3]);
                }
        }
        __syncthreads();
    }

    int grp = lane >> 2, tig = lane & 3;
#pragma unroll
    for (int mi = 0; mi < 2; mi++)
#pragma unroll
        for (int ni = 0; ni < 8; ni++) {
            int rr = m0 + wm * 32 + mi * 16 + grp;
            int cC = n0 + wn * 64 + ni * 8 + tig * 2;
            float b0 = bias[cC], b1 = bias[cC + 1];
#pragma unroll
            for (int ro = 0; ro < 2; ro++) {
                int r2 = rr + ro * 8;
                float v0 = c[mi][ni][ro * 2 + 0] + b0;
                float v1 = c[mi][ni][ro * 2 + 1] + b1;
                if (EPI == 0) {
                    v0 *= scale; v1 *= scale;
                    *(__half2*)&((__half*)out)[head_idx(r2, cC)] = __floats2half2_rn(v0, v1);
                } else {
                    *(float2*)&((float*)out)[(size_t)r2 * N + cC] = make_float2(v0, v1);
                }
            }
        }
}

// ------------------------- scores: expS + rowsums ---------------------------
__global__ __launch_bounds__(256)
void scores_kernel(const __half* __restrict__ qh, const __half* __restrict__ kh,
                   const int* __restrict__ mask, __half* __restrict__ P,
                   float* __restrict__ rowsum)
{
    constexpr int BM = 128, BN = 128, BK = 32, K = 64;
    constexpr int AS = 40, BS = 40;
    __shared__ __half As[BM * AS];
    __shared__ __half Bs[BN * BS];

    int bh = blockIdx.z;
    const __half* A = qh + (size_t)bh * Ll * 64;
    const __half* Bm = kh + (size_t)bh * Ll * 64;
    int m0 = blockIdx.y * BM, n0 = blockIdx.x * BN;

    int tid = threadIdx.x;
    int warp = tid >> 5, lane = tid & 31;
    int wm = warp >> 1, wn = warp & 1;

    float c[2][8][4];
#pragma unroll
    for (int i = 0; i < 2; i++)
#pragma unroll
        for (int j = 0; j < 8; j++)
#pragma unroll
            for (int k = 0; k < 4; k++) c[i][j][k] = 0.0f;

    for (int k0 = 0; k0 < K; k0 += BK) {
#pragma unroll
        for (int i = 0; i < 2; i++) {
            int u = tid + i * 256;
            int r = u >> 2, s = u & 3;
            *(int4*)&As[r * AS + s * 8] = *(const int4*)&A[(size_t)(m0 + r) * K + k0 + s * 8];
            *(int4*)&Bs[r * BS + s * 8] = *(const int4*)&Bm[(size_t)(n0 + r) * K + k0 + s * 8];
        }
        __syncthreads();
#pragma unroll
        for (int ks = 0; ks < 2; ks++) {
            uint32_t a[2][4];
#pragma unroll
            for (int mi = 0; mi < 2; mi++) {
                int row = wm * 32 + mi * 16 + (lane & 15);
                int col = ks * 16 + ((lane >> 4) << 3);
                ldm_x4(a[mi], sptr(&As[row * AS + col]));
            }
            uint32_t bb[4][4];
#pragma unroll
            for (int p = 0; p < 4; p++) {
                int tg = lane >> 3, idx = lane & 7;
                int row = wn * 64 + p * 16 + ((tg >> 1) << 3) + idx;
                int col = ks * 16 + ((tg & 1) << 3);
                ldm_x4(bb[p], sptr(&Bs[row * BS + col]));
            }
#pragma unroll
            for (int mi = 0; mi < 2; mi++)
#pragma unroll
                for (int p = 0; p < 4; p++) {
                    mma16816(c[mi][2 * p],     a[mi], bb[p][0], bb[p][1]);
                    mma16816(c[mi][2 * p + 1], a[mi], bb[p][2], bb[p][3]);
                }
        }
        __syncthreads();
    }

    int grp = lane >> 2, tig = lane & 3;
    int b = bh >> 3;
#pragma unroll
    for (int mi = 0; mi < 2; mi++)
#pragma unroll
        for (int ro = 0; ro < 2; ro++) {
            int q = m0 + wm * 32 + mi * 16 + grp + ro * 8;
            size_t mrow = (size_t)(b * Ll + q) * Ll;
            size_t prow = (size_t)bh * Ll * Ll + (size_t)q * Ll;
            float acc = 0.0f;
#pragma unroll
            for (int ni = 0; ni < 8; ni++) {
                int kk = n0 + wn * 64 + ni * 8 + tig * 2;
                int2 mm = *(const int2*)&mask[mrow + kk];
                float p0 = (mm.x == 1) ? 0.0f : __expf(c[mi][ni][ro * 2 + 0]);
                float p1 = (mm.y == 1) ? 0.0f : __expf(c[mi][ni][ro * 2 + 1]);
                *(__half2*)&P[prow + kk] = __floats2half2_rn(p0, p1);
                acc += p0 + p1;
            }
            acc += __shfl_xor_sync(0xffffffffu, acc, 1);
            acc += __shfl_xor_sync(0xffffffffu, acc, 2);
            if (tig == 0) atomicAdd(&rowsum[bh * Ll + q], acc);
        }
}

// ------------------------- pv: normalize + attn out + O @ permute -----------
__global__ __launch_bounds__(256)
void pv_kernel(const __half* __restrict__ Pu, const __half* __restrict__ vh,
               const float* __restrict__ invs, float* __restrict__ attn_out,
               __half* __restrict__ xin)
{
    constexpr int BM = 128, BK = 32;
    constexpr int AS = 40, BSv = 72;
    __shared__ __half As[BM * AS];
    __shared__ __half Bs[BK * BSv];

    int bh = blockIdx.y;
    int m0 = blockIdx.x * BM;
    const __half* A = Pu + (size_t)bh * Ll * Ll;
    const __half* V = vh + (size_t)bh * Ll * 64;
    float* aout = attn_out + (size_t)bh * Ll * Ll;

    int tid = threadIdx.x;
    int warp = tid >> 5, lane = tid & 31;
    int wm = warp >> 1, wn = warp & 1;   // 4 x 2 warps, warp tile 32x32

    float c[2][4][4];
#pragma unroll
    for (int i = 0; i < 2; i++)
#pragma unroll
        for (int j = 0; j < 4; j++)
#pragma unroll
            for (int k = 0; k < 4; k++) c[i][j][k] = 0.0f;

    for (int k0 = 0; k0 < Ll; k0 += BK) {
        // A tile: load fp16 expS, normalize, write fp32 attn, stash fp16 in smem
#pragma unroll
        for (int i = 0; i < 2; i++) {
            int u = tid + i * 256;
            int r = u >> 2, s = u & 3;
            int q = m0 + r;
            size_t off = (size_t)q * Ll + k0 + s * 8;
            int4 raw = *(const int4*)&A[off];
            float inv = invs[bh * Ll + q];
            __half2* ph = (__half2*)&raw;
            float2 f0 = __half22float2(ph[0]);
            float2 f1 = __half22float2(ph[1]);
            float2 f2 = __half22float2(ph[2]);
            float2 f3 = __half22float2(ph[3]);
            f0.x *= inv; f0.y *= inv; f1.x *= inv; f1.y *= inv;
            f2.x *= inv; f2.y *= inv; f3.x *= inv; f3.y *= inv;
            *(float4*)&aout[off]     = make_float4(f0.x, f0.y, f1.x, f1.y);
            *(float4*)&aout[off + 4] = make_float4(f2.x, f2.y, f3.x, f3.y);
            __half2 hh[4];
            hh[0] = __floats2half2_rn(f0.x, f0.y);
            hh[1] = __floats2half2_rn(f1.x, f1.y);
            hh[2] = __floats2half2_rn(f2.x, f2.y);
            hh[3] = __floats2half2_rn(f3.x, f3.y);
            *(int4*)&As[r * AS + s * 8] = *(int4*)hh;
        }
        // B tile: V rows k0..k0+31 x 64, natural layout (ldmatrix.trans later)
        {
            int r = tid >> 3, s = tid & 7;
            *(int4*)&Bs[r * BSv + s * 8] = *(const int4*)&V[(size_t)(k0 + r) * 64 + s * 8];
        }
        __syncthreads();
#pragma unroll
        for (int ks = 0; ks < 2; ks++) {
            uint32_t a[2][4];
#pragma unroll
            for (int mi = 0; mi < 2; mi++) {
                int row = wm * 32 + mi * 16 + (lane & 15);
                int col = ks * 16 + ((lane >> 4) << 3);
                ldm_x4(a[mi], sptr(&As[row * AS + col]));
            }
            uint32_t bb[2][4];
#pragma unroll
            for (int p = 0; p < 2; p++) {
                int tg = lane >> 3, idx = lane & 7;
                int krow = ks * 16 + ((tg & 1) << 3) + idx;
                int col = wn * 32 + p * 16 + ((tg >> 1) << 3);
                ldm_x4_t(bb[p], sptr(&Bs[krow * BSv + col]));
            }
#pragma unroll
            for (int mi = 0; mi < 2; mi++)
#pragma unroll
                for (int p = 0; p < 2; p++) {
                    mma16816(c[mi][2 * p],     a[mi], bb[p][0], bb[p][1]);
                    mma16816(c[mi][2 * p + 1], a[mi], bb[p][2], bb[p][3]);
                }
        }
        __syncthreads();
    }

    // epilogue: write xin with the reference's buffer-reinterpretation index
    int grp = lane >> 2, tig = lane & 3;
    int hp = bh >> 2, bp = bh & 3;
#pragma unroll
    for (int mi = 0; mi < 2; mi++)
#pragma unroll
        for (int ni = 0; ni < 4; ni++) {
            int rr = m0 + wm * 32 + mi * 16 + grp;
            int cC = wn * 32 + ni * 8 + tig * 2;
#pragma unroll
            for (int ro = 0; ro < 2; ro++) {
                int l = rr + ro * 8;
                size_t n = (size_t)hp * 8192 + (size_t)l * 4 + bp;
                *(__half2*)&xin[n * 64 + cC] =
                    __floats2half2_rn(c[mi][ni][ro * 2], c[mi][ni][ro * 2 + 1]);
            }
        }
}

// ------------------------- layernorm (+ residual) ---------------------------
__global__ __launch_bounds__(128)
void ln_kernel(const float* __restrict__ x2, const float* __restrict__ resid,
               const float* __restrict__ g, const float* __restrict__ bta,
               float* __restrict__ y)
{
    int r = blockIdx.x;
    const float* xr = x2 + (size_t)r * Dd;
    const float* qr = resid + (size_t)r * Dd;
    int t = threadIdx.x;
    float v[4];
    float s = 0.0f, s2 = 0.0f;
#pragma unroll
    for (int i = 0; i < 4; i++) {
        int cI = t + i * 128;
        v[i] = xr[cI] + qr[cI];
        s += v[i]; s2 += v[i] * v[i];
    }
#pragma unroll
    for (int off = 16; off > 0; off >>= 1) {
        s  += __shfl_xor_sync(0xffffffffu, s,  off);
        s2 += __shfl_xor_sync(0xffffffffu, s2, off);
    }
    __shared__ float ss[4], ss2[4];
    int w = t >> 5, lane = t & 31;
    if (lane == 0) { ss[w] = s; ss2[w] = s2; }
    __syncthreads();
    float S = ss[0] + ss[1] + ss[2] + ss[3];
    float S2 = ss2[0] + ss2[1] + ss2[2] + ss2[3];
    float mu = S / Dd;
    float var = S2 / Dd - mu * mu;
    float rstd = rsqrtf(var + LN_EPS);
#pragma unroll
    for (int i = 0; i < 4; i++) {
        int cI = t + i * 128;
        y[(size_t)r * Dd + cI] = (v[i] - mu) * rstd * g[cI] + bta[cI];
    }
}

// ------------------------- host launcher ------------------------------------
extern "C" void kernel_launch(void* const* d_in, const int* in_sizes, int n_in,
                              void* d_out, int out_size)
{
    (void)in_sizes; (void)n_in; (void)out_size;
    const float* q    = (const float*)d_in[0];
    const float* k    = (const float*)d_in[1];
    const float* v    = (const float*)d_in[2];
    const int*   mask = (const int*)d_in[3];
    const float* wq_w = (const float*)d_in[4];
    const float* wq_b = (const float*)d_in[5];
    const float* wv_w = (const float*)d_in[6];
    const float* wv_b = (const float*)d_in[7];
    const float* fc_w = (const float*)d_in[8];
    const float* fc_b = (const float*)d_in[9];
    const float* ln_g = (const float*)d_in[10];
    const float* ln_b = (const float*)d_in[11];

    float* y_out    = (float*)d_out;
    float* attn_out = y_out + (size_t)BL * Dd;

    __half *q16, *k16, *v16, *wq16, *wv16, *wf16, *qh, *kh, *vh, *P, *xin;
    float *rowsum, *x2;
    cudaGetSymbolAddress((void**)&q16,  g_q16);
    cudaGetSymbolAddress((void**)&k16,  g_k16);
    cudaGetSymbolAddress((void**)&v16,  g_v16);
    cudaGetSymbolAddress((void**)&wq16, g_wq16);
    cudaGetSymbolAddress((void**)&wv16, g_wv16);
    cudaGetSymbolAddress((void**)&wf16, g_wf16);
    cudaGetSymbolAddress((void**)&qh,   g_qh);
    cudaGetSymbolAddress((void**)&kh,   g_kh);
    cudaGetSymbolAddress((void**)&vh,   g_vh);
    cudaGetSymbolAddress((void**)&P,    g_p);
    cudaGetSymbolAddress((void**)&rowsum, g_rowsum);
    cudaGetSymbolAddress((void**)&xin,  g_xin);
    cudaGetSymbolAddress((void**)&x2,   g_x2);

    const int nBig = BL * Dd;          // 4194304
    const int nW   = Dd * Dd;          // 262144
    f2h_kernel<<<nBig / 4 / 256, 256>>>(q, q16, nBig);
    f2h_kernel<<<nBig / 4 / 256, 256>>>(k, k16, nBig);
    f2h_kernel<<<nBig / 4 / 256, 256>>>(v, v16, nBig);
    f2h_kernel<<<nW / 4 / 256, 256>>>(wq_w, wq16, nW);
    f2h_kernel<<<nW / 4 / 256, 256>>>(wv_w, wv16, nW);
    f2h_kernel<<<nW / 4 / 256, 256>>>(fc_w, wf16, nW);

    zero_kernel<<<(BH * Ll) / 256, 256>>>(rowsum, BH * Ll);

    dim3 gP(Dd / 128, BL / 128);  // (4, 64)
    gemm_kernel<0><<<gP, 256>>>(q16, wq16, wq_b, qh, Dd, Dd, INV_TEMP);
    gemm_kernel<0><<<gP, 256>>>(k16, wq16, wq_b, kh, Dd, Dd, 1.0f);   // k uses wq (bug preserved)
    gemm_kernel<0><<<gP, 256>>>(v16, wv16, wv_b, vh, Dd, Dd, 1.0f);

    scores_kernel<<<dim3(16, 16, 32), 256>>>(qh, kh, mask, P, rowsum);
    invert_kernel<<<(BH * Ll) / 256, 256>>>(rowsum, BH * Ll);
    pv_kernel<<<dim3(16, 32), 256>>>(P, vh, rowsum, attn_out, xin);

    gemm_kernel<1><<<gP, 256>>>(xin, wf16, fc_b, x2, Dd, Dd, 1.0f);
    ln_kernel<<<BL, 128>>>(x2, q, ln_g, ln_b, y_out);
}